// round 3
// baseline (speedup 1.0000x reference)
#include <cuda_runtime.h>
#include <math_constants.h>

#define NB 50
#define S51 51
#define BATCH 4096
#define NFEAT 100
#define ALPHA_INV (1.0f/0.9f)

// ---------------- device globals (scratch) ----------------------------------
__device__ float g_xm[BATCH];
__device__ float g_x[BATCH];
__device__ float g_x2[BATCH];
__device__ float g_xfinal;
__device__ float g_ccw[S51];
__device__ float g_ccs[S51];
__device__ float g_vals[BATCH * 52];

// ---------------- packed f32x2 helpers --------------------------------------
__device__ __forceinline__ unsigned long long fma2(unsigned long long a,
                                                   unsigned long long b,
                                                   unsigned long long c) {
    unsigned long long d;
    asm("fma.rn.f32x2 %0, %1, %2, %3;" : "=l"(d) : "l"(a), "l"(b), "l"(c));
    return d;
}
__device__ __forceinline__ unsigned long long pack2(float lo, float hi) {
    unsigned long long d;
    asm("mov.b64 %0, {%1, %2};" : "=l"(d) : "f"(lo), "f"(hi));
    return d;
}
__device__ __forceinline__ void unpack2(unsigned long long v, float& lo, float& hi) {
    asm("mov.b64 {%0, %1}, %2;" : "=f"(lo), "=f"(hi) : "l"(v));
}

// ---------------- SMEM layout (floats), dynamic -------------------------------
// sA: dup act buffer A [64][256]   sB: dup act buffer B [64][256]
// sW*a/sW*b: transposed half weight arrays [64][32]
#define OFF_A    0
#define OFF_B    16384
#define OFF_W1A  32768
#define OFF_W1B  34816
#define OFF_W2A  36864
#define OFF_W2B  38912
#define OFF_W0   40960      // [64][8]: 5 weights + bias
#define OFF_B1   41472
#define OFF_B2   41536
#define OFF_W3   41600
#define OFF_WF   41664
#define OFF_B3   41672
#define SMEM_FLOATS 41680
#define SMEM_BYTES (SMEM_FLOATS * 4)

// ---------------- CC weights (fp64 on device) --------------------------------
__global__ void k_init_cc() {
    int j = threadIdx.x;
    if (j > NB) return;
    double s = 0.0;
    for (int i = 0; i <= NB; ++i) {
        double w;
        if (i & 1)        w = 0.0;
        else if (i == 0)  w = 1.0;
        else              w = 2.0 / (1.0 - (double)i * (double)i);
        double l;
        if (j == 0) l = 0.5;
        else {
            l = cos((double)i * (double)j * CUDART_PI / (double)NB);
            if (j == NB) l *= 0.5;
        }
        l *= 2.0 / (double)NB;
        s += l * w;
    }
    g_ccw[j] = (float)s;
    g_ccs[j] = (float)cos((double)j * CUDART_PI / (double)NB);
}

// ---------------- xm = x_ @ log_weight ----------------------------------------
__global__ void k_xm(const float* __restrict__ x_, const float* __restrict__ lw) {
    int warp = (blockIdx.x * blockDim.x + threadIdx.x) >> 5;
    int lane = threadIdx.x & 31;
    if (warp >= BATCH) return;
    const float* row = x_ + (size_t)warp * NFEAT;
    float p = 0.f;
    for (int j = lane; j < NFEAT; j += 32) p = fmaf(row[j], lw[j], p);
    #pragma unroll
    for (int off = 16; off; off >>= 1) p += __shfl_xor_sync(0xffffffffu, p, off);
    if (lane == 0) g_xm[warp] = p;
}

// ---------------- per-step prep ------------------------------------------------
__global__ void k_prep(const float* __restrict__ sp, const float* __restrict__ out, int step) {
    __shared__ float smax[1024];
    int tid = threadIdx.x;
    float lam = 1.f / (1.f + __expf(-sp[0]));
    float lmax = -CUDART_INF_F;
    for (int b = tid; b < BATCH; b += 1024) {
        float I1v = step ? out[b]             : 0.f;
        float I2v = step ? out[2 * BATCH + b] : 0.f;
        float xmv = g_xm[b];
        float xv  = (1.f - lam) * xmv + lam * I1v;
        float x2v = (1.f - lam) * xmv + lam * I2v;
        g_x[b]  = xv;
        g_x2[b] = x2v;
        lmax = fmaxf(lmax, x2v);
    }
    smax[tid] = lmax;
    __syncthreads();
    for (int off = 512; off; off >>= 1) {
        if (tid < off) smax[tid] = fmaxf(smax[tid], smax[tid + off]);
        __syncthreads();
    }
    if (tid == 0) g_xfinal = smax[0] + 10.f;
}

// ---------------- 64->64 block GEMM layer + ReLU -------------------------------
// sIn: dup acts [k][256]; sWa/sWb: transposed half weights [k][32];
// thread tile: 4 evals (eg = tid>>3) x 8 neurons (ng = tid&7), acc over neuron pairs.
template <bool DUP_OUT>
__device__ __forceinline__ void gemm_layer(const float* __restrict__ sIn,
                                           const float* __restrict__ sWa,
                                           const float* __restrict__ sWb,
                                           const float* __restrict__ sbias,
                                           float* __restrict__ sOut, int tid) {
    const int ng = tid & 7;
    const int eg = tid >> 3;

    unsigned long long acc[4][4];
    #pragma unroll
    for (int np = 0; np < 4; ++np) {
        unsigned long long bp = *(const unsigned long long*)(sbias + ng * 8 + 2 * np);
        acc[0][np] = bp; acc[1][np] = bp; acc[2][np] = bp; acc[3][np] = bp;
    }

    const float* aPtr  = sIn + eg * 8;
    const float* waPtr = sWa + ng * 4;
    const float* wbPtr = sWb + ng * 4;

    #pragma unroll 8
    for (int k = 0; k < 64; ++k) {
        ulonglong2 a01 = *(const ulonglong2*)(aPtr + k * 256);       // (a0,a0),(a1,a1)
        ulonglong2 a23 = *(const ulonglong2*)(aPtr + k * 256 + 4);   // (a2,a2),(a3,a3)
        ulonglong2 w01 = *(const ulonglong2*)(waPtr + k * 32);       // pairs 0,1
        ulonglong2 w23 = *(const ulonglong2*)(wbPtr + k * 32);       // pairs 2,3

        acc[0][0] = fma2(w01.x, a01.x, acc[0][0]);
        acc[0][1] = fma2(w01.y, a01.x, acc[0][1]);
        acc[0][2] = fma2(w23.x, a01.x, acc[0][2]);
        acc[0][3] = fma2(w23.y, a01.x, acc[0][3]);

        acc[1][0] = fma2(w01.x, a01.y, acc[1][0]);
        acc[1][1] = fma2(w01.y, a01.y, acc[1][1]);
        acc[1][2] = fma2(w23.x, a01.y, acc[1][2]);
        acc[1][3] = fma2(w23.y, a01.y, acc[1][3]);

        acc[2][0] = fma2(w01.x, a23.x, acc[2][0]);
        acc[2][1] = fma2(w01.y, a23.x, acc[2][1]);
        acc[2][2] = fma2(w23.x, a23.x, acc[2][2]);
        acc[2][3] = fma2(w23.y, a23.x, acc[2][3]);

        acc[3][0] = fma2(w01.x, a23.y, acc[3][0]);
        acc[3][1] = fma2(w01.y, a23.y, acc[3][1]);
        acc[3][2] = fma2(w23.x, a23.y, acc[3][2]);
        acc[3][3] = fma2(w23.y, a23.y, acc[3][3]);
    }

    #pragma unroll
    for (int ee = 0; ee < 4; ++ee) {
        int Ecol = eg * 4 + ee;
        #pragma unroll
        for (int np = 0; np < 4; ++np) {
            float vlo, vhi;
            unpack2(acc[ee][np], vlo, vhi);
            vlo = fmaxf(vlo, 0.f);
            vhi = fmaxf(vhi, 0.f);
            int n0 = ng * 8 + 2 * np;
            if (DUP_OUT) {
                *(unsigned long long*)(sOut + n0 * 256 + 2 * Ecol)       = pack2(vlo, vlo);
                *(unsigned long long*)(sOut + (n0 + 1) * 256 + 2 * Ecol) = pack2(vhi, vhi);
            } else {
                sOut[n0 * 128 + Ecol]       = vlo;
                sOut[(n0 + 1) * 128 + Ecol] = vhi;
            }
        }
    }
}

// ---------------- eval kernel: 128 evals/block, block-synchronous layers -------
template <int MODE>
__global__ void __launch_bounds__(256, 1) k_eval(
    const float* __restrict__ W0, const float* __restrict__ b0,
    const float* __restrict__ W1, const float* __restrict__ b1,
    const float* __restrict__ W2, const float* __restrict__ b2,
    const float* __restrict__ W3, const float* __restrict__ b3,
    const float* __restrict__ Wf, const float* __restrict__ h,
    float* __restrict__ out)
{
    extern __shared__ float sm[];
    const int tid = threadIdx.x;

    // ---- cooperative fill: transposed half weight arrays ----
    for (int idx = tid; idx < 2048; idx += 256) {
        int m  = idx & 31;
        int k  = idx >> 5;
        int ng = m >> 2, i = m & 3;
        int nA = ng * 8 + i;
        sm[OFF_W1A + idx] = W1[nA * 64 + k];
        sm[OFF_W1B + idx] = W1[(nA + 4) * 64 + k];
        sm[OFF_W2A + idx] = W2[nA * 64 + k];
        sm[OFF_W2B + idx] = W2[(nA + 4) * 64 + k];
    }
    if (tid < 64) {
        #pragma unroll
        for (int d = 0; d < 5; ++d) sm[OFF_W0 + tid * 8 + d] = W0[tid * 5 + d];
        sm[OFF_W0 + tid * 8 + 5] = b0[tid];
        sm[OFF_B1 + tid] = b1[tid];
        sm[OFF_B2 + tid] = b2[tid];
        sm[OFF_W3 + tid] = W3[tid];
    }
    if (tid < 5)    sm[OFF_WF + tid] = Wf[tid];
    if (tid == 255) sm[OFF_B3] = b3[0];

    // ---- per-eval params (2 threads per eval) ----
    const int NS   = (MODE == 0) ? 52 : 51;
    const int e    = tid >> 1;
    const int half = tid & 1;
    const int E    = blockIdx.x * 128 + e;
    const int row  = E / NS;
    const int slot = E - row * NS;

    float lo, hi;
    if (MODE == 0) { lo = 0.f;       hi = g_x[row];  }
    else           { lo = g_x2[row]; hi = g_xfinal;  }
    const int sc = (slot < S51) ? slot : 0;
    float X = lo + (hi - lo) * (g_ccs[sc] + 1.f) * 0.5f;
    if (MODE == 0 && slot == S51) X = g_x2[row];

    const float h0 = h[row * 4 + 0], h1 = h[row * 4 + 1];
    const float h2 = h[row * 4 + 2], h3 = h[row * 4 + 3];

    __syncthreads();

    // ---- layer 0: 5 -> 64 + ReLU, write dup acts to sA ----
    {
        const int jb = half * 32;
        #pragma unroll
        for (int jj = 0; jj < 32; ++jj) {
            const float* w = sm + OFF_W0 + (jb + jj) * 8;
            float acc = w[5];
            acc = fmaf(w[0], X,  acc);
            acc = fmaf(w[1], h0, acc);
            acc = fmaf(w[2], h1, acc);
            acc = fmaf(w[3], h2, acc);
            acc = fmaf(w[4], h3, acc);
            float v = fmaxf(acc, 0.f);
            *(unsigned long long*)(sm + OFF_A + (jb + jj) * 256 + 2 * e) = pack2(v, v);
        }
    }
    __syncthreads();

    gemm_layer<true >(sm + OFF_A, sm + OFF_W1A, sm + OFF_W1B, sm + OFF_B1, sm + OFF_B, tid);
    __syncthreads();
    gemm_layer<false>(sm + OFF_B, sm + OFF_W2A, sm + OFF_W2B, sm + OFF_B2, sm + OFF_A, tid);
    __syncthreads();

    // ---- layer 3 (64->1, split over 2 threads) + epilogue ----
    float s = 0.f;
    {
        const float* actC = sm + OFF_A;   // nondup [k][128]
        const int kb = half * 32;
        #pragma unroll
        for (int kk = 0; kk < 32; ++kk)
            s = fmaf(sm[OFF_W3 + kb + kk], actC[(kb + kk) * 128 + e], s);
    }
    s += __shfl_xor_sync(0xffffffffu, s, 1);

    if (half == 0) {
        float y = s + sm[OFF_B3];
        float z  = (y > 0.f) ? (y + 1.f) : __expf(y);
        float lg = __log2f(z);

        const float P0 = (MODE == 0) ? 1.1f : 1.5f;
        const float P1 = (MODE == 0) ? 1.1f : 2.0f;
        const float P2 = (MODE == 0) ? 1.5f : 2.5f;
        const float P3 = (MODE == 0) ? 2.0f : 3.0f;
        const float P4 = (MODE == 0) ? 2.5f : 3.5f;

        float g = 0.f;
        g += __fdividef(sm[OFF_WF + 0], exp2f(P0 * lg) + 1.f);
        g += __fdividef(sm[OFF_WF + 1], exp2f(P1 * lg) + 1.f);
        g += __fdividef(sm[OFF_WF + 2], exp2f(P2 * lg) + 1.f);
        g += __fdividef(sm[OFF_WF + 3], exp2f(P3 * lg) + 1.f);
        g += __fdividef(sm[OFF_WF + 4], exp2f(P4 * lg) + 1.f);
        float val = fmaxf(g, 0.f);

        if (MODE == 0 && slot == S51) out[BATCH + row] = val;      // out_first
        else                          g_vals[row * 52 + slot] = g_ccw[sc] * val;
    }
}

// ---------------- deterministic quadrature reduce -------------------------------
template <int MODE>
__global__ void k_reduce(float* __restrict__ out) {
    int row  = blockIdx.x * 8 + (threadIdx.x >> 5);
    int lane = threadIdx.x & 31;
    const float* v = g_vals + row * 52;
    float s = v[lane];
    if (lane < 19) s += v[32 + lane];
    #pragma unroll
    for (int off = 16; off; off >>= 1) s += __shfl_xor_sync(0xffffffffu, s, off);
    if (lane == 0) {
        if (MODE == 0) out[row]             = s * g_x[row] * 0.5f;
        else           out[2 * BATCH + row] = s * (g_xfinal - g_x2[row]) * 0.5f * ALPHA_INV;
    }
}

// ---------------- launch ---------------------------------------------------------
extern "C" void kernel_launch(void* const* d_in, const int* in_sizes, int n_in,
                              void* d_out, int out_size) {
    (void)in_sizes; (void)n_in; (void)out_size;
    const float* x_ = (const float*)d_in[0];
    const float* h_ = (const float*)d_in[1];
    const float* lw = (const float*)d_in[2];
    const float* sp = (const float*)d_in[3];
    const float* f1p[9] = { (const float*)d_in[4],  (const float*)d_in[5],
                            (const float*)d_in[6],  (const float*)d_in[7],
                            (const float*)d_in[8],  (const float*)d_in[9],
                            (const float*)d_in[10], (const float*)d_in[11],
                            (const float*)d_in[12] };
    const float* f2p[9] = { (const float*)d_in[13], (const float*)d_in[14],
                            (const float*)d_in[15], (const float*)d_in[16],
                            (const float*)d_in[17], (const float*)d_in[18],
                            (const float*)d_in[19], (const float*)d_in[20],
                            (const float*)d_in[21] };
    float* out = (float*)d_out;

    cudaFuncSetAttribute(k_eval<0>, cudaFuncAttributeMaxDynamicSharedMemorySize, SMEM_BYTES);
    cudaFuncSetAttribute(k_eval<1>, cudaFuncAttributeMaxDynamicSharedMemorySize, SMEM_BYTES);

    k_init_cc<<<1, 64>>>();
    k_xm<<<BATCH / 8, 256>>>(x_, lw);

    for (int step = 0; step < 2; ++step) {
        k_prep<<<1, 1024>>>(sp, out, step);
        // MODE 0: 4096*52 = 212992 evals = 1664 blocks * 128 evals
        k_eval<0><<<1664, 256, SMEM_BYTES>>>(f1p[0], f1p[1], f1p[2], f1p[3], f1p[4],
                                             f1p[5], f1p[6], f1p[7], f1p[8], h_, out);
        k_reduce<0><<<BATCH / 8, 256>>>(out);
        // MODE 1: 4096*51 = 208896 evals = 1632 blocks * 128 evals
        k_eval<1><<<1632, 256, SMEM_BYTES>>>(f2p[0], f2p[1], f2p[2], f2p[3], f2p[4],
                                             f2p[5], f2p[6], f2p[7], f2p[8], h_, out);
        k_reduce<1><<<BATCH / 8, 256>>>(out);
    }
}

// round 4
// speedup vs baseline: 1.7041x; 1.7041x over previous
#include <cuda_runtime.h>
#include <math_constants.h>

#define NB 50
#define S51 51
#define BATCH 4096
#define NFEAT 100
#define ALPHA_INV (1.0f/0.9f)

// ---------------- device globals (scratch) ----------------------------------
__device__ float g_xm[BATCH];
__device__ float g_x[BATCH];
__device__ float g_x2[BATCH];
__device__ float g_xfinal;
__device__ float g_ccw[S51];
__device__ float g_ccs[S51];
__device__ float g_vals[BATCH * 52];

// ---------------- packed f32x2 helpers --------------------------------------
__device__ __forceinline__ unsigned long long fma2(unsigned long long a,
                                                   unsigned long long b,
                                                   unsigned long long c) {
    unsigned long long d;
    asm("fma.rn.f32x2 %0, %1, %2, %3;" : "=l"(d) : "l"(a), "l"(b), "l"(c));
    return d;
}
__device__ __forceinline__ unsigned long long pack2(float lo, float hi) {
    unsigned long long d;
    asm("mov.b64 %0, {%1, %2};" : "=l"(d) : "f"(lo), "f"(hi));
    return d;
}
__device__ __forceinline__ void unpack2(unsigned long long v, float& lo, float& hi) {
    asm("mov.b64 {%0, %1}, %2;" : "=f"(lo), "=f"(hi) : "l"(v));
}

// ---------------- SMEM layout (floats) ----------------------------------------
// sAct: per-thread column of packed (aA,aB) pairs: [64 rows][256 cols] u64
#define OFF_ACT  0            // 64*512 = 32768 floats (128KB)
#define OFF_W1T  32768        // transposed W1: [k][j], 4096 floats
#define OFF_W2T  36864        // transposed W2
#define OFF_W0   40960        // [64][8]: 5 weights + bias (+2 pad)
#define OFF_B1   41472        // 64
#define OFF_B2   41536        // 64
#define OFF_W3D  41600        // dup pairs (w3,w3): 128 floats
#define OFF_WF   41728        // 5
#define OFF_B3   41736
#define SMEM_FLOATS 41744
#define SMEM_BYTES (SMEM_FLOATS * 4)

// ---------------- CC weights (fp64 on device) --------------------------------
__global__ void k_init_cc() {
    int j = threadIdx.x;
    if (j > NB) return;
    double s = 0.0;
    for (int i = 0; i <= NB; ++i) {
        double w;
        if (i & 1)        w = 0.0;
        else if (i == 0)  w = 1.0;
        else              w = 2.0 / (1.0 - (double)i * (double)i);
        double l;
        if (j == 0) l = 0.5;
        else {
            l = cos((double)i * (double)j * CUDART_PI / (double)NB);
            if (j == NB) l *= 0.5;
        }
        l *= 2.0 / (double)NB;
        s += l * w;
    }
    g_ccw[j] = (float)s;
    g_ccs[j] = (float)cos((double)j * CUDART_PI / (double)NB);
}

// ---------------- xm = x_ @ log_weight ----------------------------------------
__global__ void k_xm(const float* __restrict__ x_, const float* __restrict__ lw) {
    int warp = (blockIdx.x * blockDim.x + threadIdx.x) >> 5;
    int lane = threadIdx.x & 31;
    if (warp >= BATCH) return;
    const float* row = x_ + (size_t)warp * NFEAT;
    float p = 0.f;
    for (int j = lane; j < NFEAT; j += 32) p = fmaf(row[j], lw[j], p);
    #pragma unroll
    for (int off = 16; off; off >>= 1) p += __shfl_xor_sync(0xffffffffu, p, off);
    if (lane == 0) g_xm[warp] = p;
}

// ---------------- per-step prep ------------------------------------------------
__global__ void k_prep(const float* __restrict__ sp, const float* __restrict__ out, int step) {
    __shared__ float smax[1024];
    int tid = threadIdx.x;
    float lam = 1.f / (1.f + __expf(-sp[0]));
    float lmax = -CUDART_INF_F;
    for (int b = tid; b < BATCH; b += 1024) {
        float I1v = step ? out[b]             : 0.f;
        float I2v = step ? out[2 * BATCH + b] : 0.f;
        float xmv = g_xm[b];
        g_x[b]  = (1.f - lam) * xmv + lam * I1v;
        float x2v = (1.f - lam) * xmv + lam * I2v;
        g_x2[b] = x2v;
        lmax = fmaxf(lmax, x2v);
    }
    smax[tid] = lmax;
    __syncthreads();
    for (int off = 512; off; off >>= 1) {
        if (tid < off) smax[tid] = fmaxf(smax[tid], smax[tid + off]);
        __syncthreads();
    }
    if (tid == 0) g_xfinal = smax[0] + 10.f;
}

// ---------------- 64->64 layer for 2 packed evals -----------------------------
// sWT: transposed weights [k][j] (j fast). sbias: plain biases.
// Acts read from / written to per-thread smem column (packed (aA,aB) u64),
// in-place: all reads precede all writes, column is thread-private.
__device__ __forceinline__ void layer64x2(const float* __restrict__ sWT,
                                          const float* __restrict__ sbias,
                                          float* __restrict__ sActCol /* + 2*tid */) {
    unsigned long long acc0[32], acc1[32];
    #pragma unroll
    for (int jp = 0; jp < 32; ++jp) {
        unsigned long long bp = *(const unsigned long long*)(sbias + 2 * jp);
        acc0[jp] = bp;
        acc1[jp] = bp;
    }

    #pragma unroll 1
    for (int k = 0; k < 64; ++k) {
        unsigned long long ap = *(const unsigned long long*)(sActCol + k * 512);
        float aA, aB;
        unpack2(ap, aA, aB);
        unsigned long long a2A = pack2(aA, aA);
        unsigned long long a2B = pack2(aB, aB);
        const ulonglong2* w = (const ulonglong2*)(sWT + k * 64);
        #pragma unroll
        for (int q = 0; q < 16; ++q) {
            ulonglong2 wv = w[q];                 // warp-uniform -> broadcast LDS.128
            acc0[2 * q]     = fma2(wv.x, a2A, acc0[2 * q]);
            acc0[2 * q + 1] = fma2(wv.y, a2A, acc0[2 * q + 1]);
            acc1[2 * q]     = fma2(wv.x, a2B, acc1[2 * q]);
            acc1[2 * q + 1] = fma2(wv.y, a2B, acc1[2 * q + 1]);
        }
    }

    // ReLU + repack (neuron-pair packing -> eval packing) + store
    #pragma unroll
    for (int jp = 0; jp < 32; ++jp) {
        float a0, a1, b0v, b1v;
        unpack2(acc0[jp], a0, a1);   // eval A, neurons 2jp, 2jp+1
        unpack2(acc1[jp], b0v, b1v); // eval B
        a0 = fmaxf(a0, 0.f); a1 = fmaxf(a1, 0.f);
        b0v = fmaxf(b0v, 0.f); b1v = fmaxf(b1v, 0.f);
        *(unsigned long long*)(sActCol + (2 * jp) * 512)     = pack2(a0, b0v);
        *(unsigned long long*)(sActCol + (2 * jp + 1) * 512) = pack2(a1, b1v);
    }
}

// ---------------- eval kernel: 512 evals/block, 2 per thread -------------------
template <int MODE>
__global__ void __launch_bounds__(256, 1) k_eval(
    const float* __restrict__ W0, const float* __restrict__ b0,
    const float* __restrict__ W1, const float* __restrict__ b1,
    const float* __restrict__ W2, const float* __restrict__ b2,
    const float* __restrict__ W3, const float* __restrict__ b3,
    const float* __restrict__ Wf, const float* __restrict__ h,
    float* __restrict__ out)
{
    extern __shared__ float sm[];
    const int tid = threadIdx.x;

    // ---- cooperative fill ----
    for (int idx = tid; idx < 4096; idx += 256) {
        int k = idx >> 6, j = idx & 63;          // smem-store conflict-free; gmem reads L2-cached
        sm[OFF_W1T + idx] = W1[j * 64 + k];
        sm[OFF_W2T + idx] = W2[j * 64 + k];
    }
    if (tid < 64) {
        #pragma unroll
        for (int d = 0; d < 5; ++d) sm[OFF_W0 + tid * 8 + d] = W0[tid * 5 + d];
        sm[OFF_W0 + tid * 8 + 5] = b0[tid];
        sm[OFF_B1 + tid] = b1[tid];
        sm[OFF_B2 + tid] = b2[tid];
        float w3 = W3[tid];
        sm[OFF_W3D + 2 * tid]     = w3;
        sm[OFF_W3D + 2 * tid + 1] = w3;
    }
    if (tid < 5)    sm[OFF_WF + tid] = Wf[tid];
    if (tid == 255) sm[OFF_B3] = b3[0];

    // ---- per-eval params (2 evals per thread) ----
    const int NS = (MODE == 0) ? 52 : 51;
    const int E0 = (blockIdx.x * 256 + tid) * 2;
    const int E1 = E0 + 1;
    const int row0 = E0 / NS, slot0 = E0 - row0 * NS;
    const int row1 = E1 / NS, slot1 = E1 - row1 * NS;

    float XA, XB;
    {
        float lo, hi;
        if (MODE == 0) { lo = 0.f;        hi = g_x[row0]; }
        else           { lo = g_x2[row0]; hi = g_xfinal;  }
        int sc = (slot0 < S51) ? slot0 : 0;
        XA = lo + (hi - lo) * (g_ccs[sc] + 1.f) * 0.5f;
        if (MODE == 0 && slot0 == S51) XA = g_x2[row0];
    }
    {
        float lo, hi;
        if (MODE == 0) { lo = 0.f;        hi = g_x[row1]; }
        else           { lo = g_x2[row1]; hi = g_xfinal;  }
        int sc = (slot1 < S51) ? slot1 : 0;
        XB = lo + (hi - lo) * (g_ccs[sc] + 1.f) * 0.5f;
        if (MODE == 0 && slot1 == S51) XB = g_x2[row1];
    }
    const float hA0 = h[row0 * 4 + 0], hA1 = h[row0 * 4 + 1];
    const float hA2 = h[row0 * 4 + 2], hA3 = h[row0 * 4 + 3];
    const float hB0 = h[row1 * 4 + 0], hB1 = h[row1 * 4 + 1];
    const float hB2 = h[row1 * 4 + 2], hB3 = h[row1 * 4 + 3];

    __syncthreads();

    float* actCol = sm + OFF_ACT + 2 * tid;

    // ---- layer 0: 5 -> 64 + ReLU, write packed (aA,aB) ----
    #pragma unroll 4
    for (int j = 0; j < 64; ++j) {
        const float* w = sm + OFF_W0 + j * 8;     // broadcast
        float w0 = w[0], w1 = w[1], w2 = w[2], w3v = w[3], w4 = w[4], bb = w[5];
        float aA = bb, aB = bb;
        aA = fmaf(w0, XA,  aA);  aB = fmaf(w0, XB,  aB);
        aA = fmaf(w1, hA0, aA);  aB = fmaf(w1, hB0, aB);
        aA = fmaf(w2, hA1, aA);  aB = fmaf(w2, hB1, aB);
        aA = fmaf(w3v, hA2, aA); aB = fmaf(w3v, hB2, aB);
        aA = fmaf(w4, hA3, aA);  aB = fmaf(w4, hB3, aB);
        *(unsigned long long*)(actCol + j * 512) = pack2(fmaxf(aA, 0.f), fmaxf(aB, 0.f));
    }

    // ---- layers 1,2 ----
    layer64x2(sm + OFF_W1T, sm + OFF_B1, actCol);
    layer64x2(sm + OFF_W2T, sm + OFF_B2, actCol);

    // ---- layer 3: 64 -> 1 for both evals (packed) ----
    unsigned long long yacc = pack2(sm[OFF_B3], sm[OFF_B3]);
    #pragma unroll 8
    for (int k = 0; k < 64; ++k) {
        unsigned long long ap = *(const unsigned long long*)(actCol + k * 512);
        unsigned long long wd = *(const unsigned long long*)(sm + OFF_W3D + 2 * k); // (w,w) broadcast
        yacc = fma2(wd, ap, yacc);
    }
    float yA, yB;
    unpack2(yacc, yA, yB);

    // ---- epilogue per eval ----
    const float P0 = (MODE == 0) ? 1.1f : 1.5f;
    const float P1 = (MODE == 0) ? 1.1f : 2.0f;
    const float P2 = (MODE == 0) ? 1.5f : 2.5f;
    const float P3 = (MODE == 0) ? 2.0f : 3.0f;
    const float P4 = (MODE == 0) ? 2.5f : 3.5f;
    const float wf0 = sm[OFF_WF + 0], wf1 = sm[OFF_WF + 1], wf2 = sm[OFF_WF + 2];
    const float wf3 = sm[OFF_WF + 3], wf4 = sm[OFF_WF + 4];

    #pragma unroll
    for (int e = 0; e < 2; ++e) {
        float y    = e ? yB : yA;
        int   row  = e ? row1 : row0;
        int   slot = e ? slot1 : slot0;
        float z  = (y > 0.f) ? (y + 1.f) : __expf(y);
        float lg = __log2f(z);
        float g = 0.f;
        g += __fdividef(wf0, exp2f(P0 * lg) + 1.f);
        g += __fdividef(wf1, exp2f(P1 * lg) + 1.f);
        g += __fdividef(wf2, exp2f(P2 * lg) + 1.f);
        g += __fdividef(wf3, exp2f(P3 * lg) + 1.f);
        g += __fdividef(wf4, exp2f(P4 * lg) + 1.f);
        float val = fmaxf(g, 0.f);

        if (MODE == 0 && slot == S51) out[BATCH + row] = val;          // out_first
        else g_vals[row * 52 + slot] = g_ccw[slot] * val;
    }
}

// ---------------- deterministic quadrature reduce -------------------------------
template <int MODE>
__global__ void k_reduce(float* __restrict__ out) {
    int row  = blockIdx.x * 8 + (threadIdx.x >> 5);
    int lane = threadIdx.x & 31;
    const float* v = g_vals + row * 52;
    float s = v[lane];
    if (lane < 19) s += v[32 + lane];
    #pragma unroll
    for (int off = 16; off; off >>= 1) s += __shfl_xor_sync(0xffffffffu, s, off);
    if (lane == 0) {
        if (MODE == 0) out[row]             = s * g_x[row] * 0.5f;
        else           out[2 * BATCH + row] = s * (g_xfinal - g_x2[row]) * 0.5f * ALPHA_INV;
    }
}

// ---------------- launch ---------------------------------------------------------
extern "C" void kernel_launch(void* const* d_in, const int* in_sizes, int n_in,
                              void* d_out, int out_size) {
    (void)in_sizes; (void)n_in; (void)out_size;
    const float* x_ = (const float*)d_in[0];
    const float* h_ = (const float*)d_in[1];
    const float* lw = (const float*)d_in[2];
    const float* sp = (const float*)d_in[3];
    const float* f1p[9] = { (const float*)d_in[4],  (const float*)d_in[5],
                            (const float*)d_in[6],  (const float*)d_in[7],
                            (const float*)d_in[8],  (const float*)d_in[9],
                            (const float*)d_in[10], (const float*)d_in[11],
                            (const float*)d_in[12] };
    const float* f2p[9] = { (const float*)d_in[13], (const float*)d_in[14],
                            (const float*)d_in[15], (const float*)d_in[16],
                            (const float*)d_in[17], (const float*)d_in[18],
                            (const float*)d_in[19], (const float*)d_in[20],
                            (const float*)d_in[21] };
    float* out = (float*)d_out;

    cudaFuncSetAttribute(k_eval<0>, cudaFuncAttributeMaxDynamicSharedMemorySize, SMEM_BYTES);
    cudaFuncSetAttribute(k_eval<1>, cudaFuncAttributeMaxDynamicSharedMemorySize, SMEM_BYTES);

    k_init_cc<<<1, 64>>>();
    k_xm<<<BATCH / 8, 256>>>(x_, lw);

    for (int step = 0; step < 2; ++step) {
        k_prep<<<1, 1024>>>(sp, out, step);
        // MODE 0: 4096*52 = 212992 evals = 416 blocks * 512 evals
        k_eval<0><<<416, 256, SMEM_BYTES>>>(f1p[0], f1p[1], f1p[2], f1p[3], f1p[4],
                                            f1p[5], f1p[6], f1p[7], f1p[8], h_, out);
        k_reduce<0><<<BATCH / 8, 256>>>(out);
        // MODE 1: 4096*51 = 208896 evals = 408 blocks * 512 evals
        k_eval<1><<<408, 256, SMEM_BYTES>>>(f2p[0], f2p[1], f2p[2], f2p[3], f2p[4],
                                            f2p[5], f2p[6], f2p[7], f2p[8], h_, out);
        k_reduce<1><<<BATCH / 8, 256>>>(out);
    }
}